// round 1
// baseline (speedup 1.0000x reference)
#include <cuda_runtime.h>
#include <cstdint>

// Problem constants (match reference_code)
#define NUM_USERS 200000
#define NUM_ITEMS 100000
#define EMB_DIM   64
#define D4        (EMB_DIM / 4)   // 16 float4 lanes per node

// ---------------------------------------------------------------------------
// Scratch: __device__ globals (no allocation allowed in kernel_launch)
// ---------------------------------------------------------------------------
__device__ float g_sum_user[(size_t)NUM_USERS * EMB_DIM];   // 51.2 MB
__device__ float g_sum_item[(size_t)NUM_ITEMS * EMB_DIM];   // 25.6 MB
__device__ float g_u1[(size_t)NUM_USERS * EMB_DIM];         // 51.2 MB
__device__ float g_i1[(size_t)NUM_ITEMS * EMB_DIM];         // 25.6 MB
__device__ float g_deg_user[NUM_USERS];
__device__ float g_deg_item[NUM_ITEMS];

// ---------------------------------------------------------------------------
// Vector reduction helper: red.global.add.v4.f32 (sm_90+)
// ---------------------------------------------------------------------------
__device__ __forceinline__ void red_add_v4(float* p, float4 v) {
    asm volatile("red.global.add.v4.f32 [%0], {%1, %2, %3, %4};"
                 :: "l"(p), "f"(v.x), "f"(v.y), "f"(v.z), "f"(v.w)
                 : "memory");
}

// ---------------------------------------------------------------------------
// Zero accumulators (and degrees on first pass)
// ---------------------------------------------------------------------------
__global__ void k_zero(int with_deg) {
    const long n_u4 = (long)NUM_USERS * D4;
    const long n_i4 = (long)NUM_ITEMS * D4;
    long t      = (long)blockIdx.x * blockDim.x + threadIdx.x;
    long stride = (long)gridDim.x * blockDim.x;
    float4 z = make_float4(0.f, 0.f, 0.f, 0.f);
    float4* su = reinterpret_cast<float4*>(g_sum_user);
    float4* si = reinterpret_cast<float4*>(g_sum_item);
    for (long i = t; i < n_u4; i += stride) su[i] = z;
    for (long i = t; i < n_i4; i += stride) si[i] = z;
    if (with_deg) {
        for (long i = t; i < NUM_USERS; i += stride) g_deg_user[i] = 0.f;
        for (long i = t; i < NUM_ITEMS; i += stride) g_deg_item[i] = 0.f;
    }
}

// ---------------------------------------------------------------------------
// Edge degree counting (one thread per edge)
// ---------------------------------------------------------------------------
__global__ void k_count(const int* __restrict__ src, const int* __restrict__ dst,
                        int num_edges) {
    int e = blockIdx.x * blockDim.x + threadIdx.x;
    if (e >= num_edges) return;
    atomicAdd(&g_deg_item[dst[e]], 1.0f);
    atomicAdd(&g_deg_user[src[e]], 1.0f);
}

// ---------------------------------------------------------------------------
// Bipartite scatter: 16 threads per edge, each owns one float4 lane.
// Pushes u[src] into item sums AND i[dst] into user sums in one pass
// (index loads amortized across both directions).
// layer2 != 0 -> read from scratch u1/i1 instead of the kernel inputs.
// ---------------------------------------------------------------------------
__global__ void k_scatter(const float4* __restrict__ u_in,
                          const float4* __restrict__ i_in,
                          const int* __restrict__ src,
                          const int* __restrict__ dst,
                          int num_edges, int layer2) {
    long t = (long)blockIdx.x * blockDim.x + threadIdx.x;
    int e    = (int)(t >> 4);
    int lane = (int)(t & 15);
    if (e >= num_edges) return;

    const float4* u = layer2 ? reinterpret_cast<const float4*>(g_u1) : u_in;
    const float4* v = layer2 ? reinterpret_cast<const float4*>(g_i1) : i_in;

    int s = __ldg(src + e);
    int d = __ldg(dst + e);

    float4 uv = __ldg(&u[(long)s * D4 + lane]);   // user feature -> item sum
    float4 iv = __ldg(&v[(long)d * D4 + lane]);   // item feature -> user sum

    red_add_v4(g_sum_item + ((long)d * EMB_DIM + lane * 4), uv);
    red_add_v4(g_sum_user + ((long)s * EMB_DIM + lane * 4), iv);
}

// ---------------------------------------------------------------------------
// Normalize layer-1 sums into u1 / i1 scratch
// ---------------------------------------------------------------------------
__global__ void k_norm1() {
    const long n_u4 = (long)NUM_USERS * D4;
    const long n_i4 = (long)NUM_ITEMS * D4;
    long t      = (long)blockIdx.x * blockDim.x + threadIdx.x;
    long stride = (long)gridDim.x * blockDim.x;

    const float4* su = reinterpret_cast<const float4*>(g_sum_user);
    const float4* si = reinterpret_cast<const float4*>(g_sum_item);
    float4* u1 = reinterpret_cast<float4*>(g_u1);
    float4* i1 = reinterpret_cast<float4*>(g_i1);

    for (long i = t; i < n_u4; i += stride) {
        float dg  = g_deg_user[i >> 4];
        float inv = dg > 0.f ? 1.f / dg : 0.f;
        float4 s = su[i];
        u1[i] = make_float4(s.x * inv, s.y * inv, s.z * inv, s.w * inv);
    }
    for (long i = t; i < n_i4; i += stride) {
        float dg  = g_deg_item[i >> 4];
        float inv = dg > 0.f ? 1.f / dg : 0.f;
        float4 s = si[i];
        i1[i] = make_float4(s.x * inv, s.y * inv, s.z * inv, s.w * inv);
    }
}

// ---------------------------------------------------------------------------
// Final combine: out_user = (u0 + u1 + u2)/3 ; out_item = (i0 + i1 + i2)/3
// u2/i2 computed on the fly from layer-2 sums + degrees.
// Output layout: [NUM_USERS*64] then [NUM_ITEMS*64].
// ---------------------------------------------------------------------------
__global__ void k_final(const float4* __restrict__ u0,
                        const float4* __restrict__ i0,
                        float4* __restrict__ out) {
    const long n_u4 = (long)NUM_USERS * D4;
    const long n_i4 = (long)NUM_ITEMS * D4;
    long t      = (long)blockIdx.x * blockDim.x + threadIdx.x;
    long stride = (long)gridDim.x * blockDim.x;
    const float third = 1.0f / 3.0f;

    const float4* su = reinterpret_cast<const float4*>(g_sum_user);
    const float4* si = reinterpret_cast<const float4*>(g_sum_item);
    const float4* u1 = reinterpret_cast<const float4*>(g_u1);
    const float4* i1 = reinterpret_cast<const float4*>(g_i1);

    for (long i = t; i < n_u4; i += stride) {
        float dg  = g_deg_user[i >> 4];
        float inv = dg > 0.f ? 1.f / dg : 0.f;
        float4 a = u0[i], b = u1[i], s = su[i];
        out[i] = make_float4((a.x + b.x + s.x * inv) * third,
                             (a.y + b.y + s.y * inv) * third,
                             (a.z + b.z + s.z * inv) * third,
                             (a.w + b.w + s.w * inv) * third);
    }
    for (long i = t; i < n_i4; i += stride) {
        float dg  = g_deg_item[i >> 4];
        float inv = dg > 0.f ? 1.f / dg : 0.f;
        float4 a = i0[i], b = i1[i], s = si[i];
        out[n_u4 + i] = make_float4((a.x + b.x + s.x * inv) * third,
                                    (a.y + b.y + s.y * inv) * third,
                                    (a.z + b.z + s.z * inv) * third,
                                    (a.w + b.w + s.w * inv) * third);
    }
}

// ---------------------------------------------------------------------------
// kernel_launch: 7 launches, all graph-capturable, no allocation.
// ---------------------------------------------------------------------------
extern "C" void kernel_launch(void* const* d_in, const int* in_sizes, int n_in,
                              void* d_out, int out_size) {
    const float4* user_emb = (const float4*)d_in[0];
    const float4* item_emb = (const float4*)d_in[1];
    const int*    src      = (const int*)d_in[2];
    const int*    dst      = (const int*)d_in[3];
    const int     E        = in_sizes[2];
    float4*       out      = (float4*)d_out;

    const int TPB = 256;
    const int zero_blocks  = 2048;
    const int norm_blocks  = 2048;
    const int count_blocks = (E + TPB - 1) / TPB;
    // 16 threads per edge for scatter
    const long scat_threads = (long)E * 16;
    const int  scat_blocks  = (int)((scat_threads + TPB - 1) / TPB);

    // Layer 1
    k_zero<<<zero_blocks, TPB>>>(1);
    k_count<<<count_blocks, TPB>>>(src, dst, E);
    k_scatter<<<scat_blocks, TPB>>>(user_emb, item_emb, src, dst, E, 0);
    k_norm1<<<norm_blocks, TPB>>>();

    // Layer 2
    k_zero<<<zero_blocks, TPB>>>(0);
    k_scatter<<<scat_blocks, TPB>>>(user_emb, item_emb, src, dst, E, 1);

    // Combine
    k_final<<<norm_blocks, TPB>>>(user_emb, item_emb, out);
}

// round 2
// speedup vs baseline: 1.8541x; 1.8541x over previous
#include <cuda_runtime.h>
#include <cstdint>

#define NUM_USERS 200000
#define NUM_ITEMS 100000
#define N_NODES   (NUM_USERS + NUM_ITEMS)     // 300000, users first then items
#define EMB_DIM   64
#define D2        (EMB_DIM / 2)               // 32 float2 lanes per row
#define MAX_EDGES 3000000

#define SCAN_TPB    1024
#define SCAN_BLOCKS ((N_NODES + SCAN_TPB - 1) / SCAN_TPB)   // 293

// ---------------------------------------------------------------------------
// Scratch (__device__ globals; no allocation allowed)
// ---------------------------------------------------------------------------
__device__ int   g_deg[N_NODES];
__device__ int   g_off[N_NODES];
__device__ int   g_cursor[N_NODES];
__device__ int   g_bsum[SCAN_BLOCKS];
__device__ int   g_bbase[SCAN_BLOCKS];
__device__ int   g_adj[2 * MAX_EDGES];                       // combined CSR, 24 MB
__device__ float g_u1[(size_t)NUM_USERS * EMB_DIM];          // 51.2 MB
__device__ float g_i1[(size_t)NUM_ITEMS * EMB_DIM];          // 25.6 MB

// ---------------------------------------------------------------------------
// 0. zero degrees
// ---------------------------------------------------------------------------
__global__ void k_zerodeg() {
    int t = blockIdx.x * blockDim.x + threadIdx.x;
    int stride = gridDim.x * blockDim.x;
    for (int i = t; i < N_NODES; i += stride) g_deg[i] = 0;
}

// ---------------------------------------------------------------------------
// 1. degree histogram (both directions in one pass)
// ---------------------------------------------------------------------------
__global__ void k_count(const int* __restrict__ src, const int* __restrict__ dst,
                        int num_edges) {
    int e = blockIdx.x * blockDim.x + threadIdx.x;
    if (e >= num_edges) return;
    atomicAdd(&g_deg[src[e]], 1);
    atomicAdd(&g_deg[NUM_USERS + dst[e]], 1);
}

// ---------------------------------------------------------------------------
// 2-4. exclusive prefix scan over g_deg -> g_off (3 kernels)
// ---------------------------------------------------------------------------
__global__ void k_scan1() {
    __shared__ int sh[SCAN_TPB];
    int tid = threadIdx.x;
    int gid = blockIdx.x * SCAN_TPB + tid;
    int v = (gid < N_NODES) ? g_deg[gid] : 0;
    sh[tid] = v;
    __syncthreads();
    for (int ofs = 1; ofs < SCAN_TPB; ofs <<= 1) {
        int t = 0;
        if (tid >= ofs) t = sh[tid - ofs];
        __syncthreads();
        sh[tid] += t;
        __syncthreads();
    }
    int incl = sh[tid];
    if (gid < N_NODES) g_off[gid] = incl - v;                 // block-local exclusive
    if (tid == SCAN_TPB - 1) g_bsum[blockIdx.x] = incl;
}

__global__ void k_scan2() {
    __shared__ int sh[512];
    int tid = threadIdx.x;
    int v = (tid < SCAN_BLOCKS) ? g_bsum[tid] : 0;
    sh[tid] = v;
    __syncthreads();
    for (int ofs = 1; ofs < 512; ofs <<= 1) {
        int t = 0;
        if (tid >= ofs) t = sh[tid - ofs];
        __syncthreads();
        sh[tid] += t;
        __syncthreads();
    }
    if (tid < SCAN_BLOCKS) g_bbase[tid] = sh[tid] - v;        // exclusive block base
}

__global__ void k_scan3() {
    int gid = blockIdx.x * SCAN_TPB + threadIdx.x;
    if (gid < N_NODES) {
        int v = g_off[gid] + g_bbase[blockIdx.x];
        g_off[gid]    = v;
        g_cursor[gid] = v;
    }
}

// ---------------------------------------------------------------------------
// 5. bin edges into combined CSR (user rows hold item ids, item rows user ids)
// ---------------------------------------------------------------------------
__global__ void k_bin(const int* __restrict__ src, const int* __restrict__ dst,
                      int num_edges) {
    int e = blockIdx.x * blockDim.x + threadIdx.x;
    if (e >= num_edges) return;
    int s = src[e], d = dst[e];
    g_adj[atomicAdd(&g_cursor[s], 1)]             = d;
    g_adj[atomicAdd(&g_cursor[NUM_USERS + d], 1)] = s;
}

// ---------------------------------------------------------------------------
// Warp-level mean gather: one warp per node, float2 per lane (256B/row LDG)
// ---------------------------------------------------------------------------
__device__ __forceinline__ float2 warp_gather_mean(int node, int lane,
                                                   const float2* __restrict__ tab) {
    int off = g_off[node];
    int deg = g_deg[node];
    float ax = 0.f, ay = 0.f;
    for (int base = 0; base < deg; base += 32) {
        int nidx = 0;
        if (base + lane < deg) nidx = __ldg(&g_adj[off + base + lane]);
        int lim = min(32, deg - base);
        int k = 0;
        for (; k + 4 <= lim; k += 4) {                        // MLP=4
            int n0 = __shfl_sync(0xffffffffu, nidx, k);
            int n1 = __shfl_sync(0xffffffffu, nidx, k + 1);
            int n2 = __shfl_sync(0xffffffffu, nidx, k + 2);
            int n3 = __shfl_sync(0xffffffffu, nidx, k + 3);
            float2 v0 = __ldg(&tab[(long)n0 * D2 + lane]);
            float2 v1 = __ldg(&tab[(long)n1 * D2 + lane]);
            float2 v2 = __ldg(&tab[(long)n2 * D2 + lane]);
            float2 v3 = __ldg(&tab[(long)n3 * D2 + lane]);
            ax += v0.x + v1.x + v2.x + v3.x;
            ay += v0.y + v1.y + v2.y + v3.y;
        }
        for (; k < lim; k++) {
            int nb = __shfl_sync(0xffffffffu, nidx, k);
            float2 v = __ldg(&tab[(long)nb * D2 + lane]);
            ax += v.x; ay += v.y;
        }
    }
    float inv = deg > 0 ? 1.f / (float)deg : 0.f;
    return make_float2(ax * inv, ay * inv);
}

// ---------------------------------------------------------------------------
// 6. layer-1 pull: u1 = mean(i0 over user's items); i1 = mean(u0 over item's users)
// ---------------------------------------------------------------------------
__global__ void k_pull1(const float2* __restrict__ u0, const float2* __restrict__ i0) {
    int warp = (blockIdx.x * blockDim.x + threadIdx.x) >> 5;
    int lane = threadIdx.x & 31;
    if (warp >= N_NODES) return;

    bool is_user = warp < NUM_USERS;
    const float2* tab = is_user ? i0 : u0;
    float2 m = warp_gather_mean(warp, lane, tab);

    if (is_user) reinterpret_cast<float2*>(g_u1)[(long)warp * D2 + lane] = m;
    else         reinterpret_cast<float2*>(g_i1)[(long)(warp - NUM_USERS) * D2 + lane] = m;
}

// ---------------------------------------------------------------------------
// 7. layer-2 pull fused with final combine:
//    out[n] = (x0 + x1 + mean_neighbors(x1_other)) / 3
//    Output layout: users then items == combined node order.
// ---------------------------------------------------------------------------
__global__ void k_pull2(const float2* __restrict__ u0, const float2* __restrict__ i0,
                        float2* __restrict__ out) {
    int warp = (blockIdx.x * blockDim.x + threadIdx.x) >> 5;
    int lane = threadIdx.x & 31;
    if (warp >= N_NODES) return;

    bool is_user = warp < NUM_USERS;
    const float2* tab = is_user ? reinterpret_cast<const float2*>(g_i1)
                                : reinterpret_cast<const float2*>(g_u1);
    float2 m = warp_gather_mean(warp, lane, tab);             // x2

    long row = is_user ? warp : (warp - NUM_USERS);
    const float2* t0 = is_user ? u0 : i0;
    const float2* t1 = is_user ? reinterpret_cast<const float2*>(g_u1)
                               : reinterpret_cast<const float2*>(g_i1);
    float2 a = __ldg(&t0[row * D2 + lane]);
    float2 b = __ldg(&t1[row * D2 + lane]);
    const float third = 1.0f / 3.0f;
    out[(long)warp * D2 + lane] =
        make_float2((a.x + b.x + m.x) * third, (a.y + b.y + m.y) * third);
}

// ---------------------------------------------------------------------------
// kernel_launch
// ---------------------------------------------------------------------------
extern "C" void kernel_launch(void* const* d_in, const int* in_sizes, int n_in,
                              void* d_out, int out_size) {
    const float2* user_emb = (const float2*)d_in[0];
    const float2* item_emb = (const float2*)d_in[1];
    const int*    src      = (const int*)d_in[2];
    const int*    dst      = (const int*)d_in[3];
    const int     E        = in_sizes[2];
    float2*       out      = (float2*)d_out;

    const int TPB = 256;
    const int edge_blocks = (E + TPB - 1) / TPB;
    const long pull_threads = (long)N_NODES * 32;
    const int  pull_blocks  = (int)((pull_threads + TPB - 1) / TPB);

    k_zerodeg<<<256, TPB>>>();
    k_count<<<edge_blocks, TPB>>>(src, dst, E);
    k_scan1<<<SCAN_BLOCKS, SCAN_TPB>>>();
    k_scan2<<<1, 512>>>();
    k_scan3<<<SCAN_BLOCKS, SCAN_TPB>>>();
    k_bin<<<edge_blocks, TPB>>>(src, dst, E);

    k_pull1<<<pull_blocks, TPB>>>(user_emb, item_emb);
    k_pull2<<<pull_blocks, TPB>>>(user_emb, item_emb, out);
}